// round 16
// baseline (speedup 1.0000x reference)
#include <cuda_runtime.h>
#include <cuda_fp16.h>
#include <math.h>

#define S 1024
#define B 128
#define E 10
#define H 256
#define L 4
#define G4 1024           // 4*H
#define NBPL 32           // blocks per layer
#define NBLK (NBPL * L)   // 128 persistent blocks

// ---------------- device scratch (static; no allocations) ----------------
// fp16 weight fragments: [l][nb][kt][nt][lane] = uint2(w.k01, w.k89)
__device__ __align__(8) uint2  g_Wp[4 * 32 * 32 * 4 * 32];
__device__ float  g_bias[4 * 32 * 32];
__device__ float  g_w0p[32 * 32 * 10];
__device__ float  g_S[S * B * E];
__device__ float  g_C0[L * B * H];
// h state: [l][slot(4)][b][64 uint4]; u64 unit = (hi(j),hi(j+1),lo(j),lo(j+1)) fp16
__device__ __align__(16) uint4 g_Hq[L * 4 * B * 64];
// fine-grained counters: [l][nb][w] = steps published (t+1 after step t); single writer
__device__ int g_fine[L * 32 * 8];

// ---------------- helpers ----------------
// perm-unit index for even col j: u64-unit within row
__device__ __host__ __forceinline__ int unitj(int j) {
    return (j >> 4) * 8 + (j & 6) + ((j >> 3) & 1);
}

__device__ __forceinline__ unsigned pk(__half a, __half b) {
    __half2 t; t.x = a; t.y = b;
    return *reinterpret_cast<unsigned*>(&t);
}

__device__ __forceinline__ void mma16816(float c[4], const unsigned a[4],
                                         unsigned b0, unsigned b1) {
    asm("mma.sync.aligned.m16n8k16.row.col.f32.f16.f16.f32 "
        "{%0,%1,%2,%3},{%4,%5,%6,%7},{%8,%9},{%0,%1,%2,%3};"
        : "+f"(c[0]), "+f"(c[1]), "+f"(c[2]), "+f"(c[3])
        : "r"(a[0]), "r"(a[1]), "r"(a[2]), "r"(a[3]), "r"(b0), "r"(b1));
}

__device__ __forceinline__ float fsig(float x) {
    return __fdividef(1.0f, 1.0f + __expf(-x));
}
__device__ __forceinline__ float ftanh(float x) {
    return 1.0f - __fdividef(2.0f, __expf(2.0f * x) + 1.0f);
}

__device__ __forceinline__ int ld_acq(const int* p) {
    int v;
    asm volatile("ld.acquire.gpu.global.b32 %0, [%1];" : "=r"(v) : "l"(p) : "memory");
    return v;
}
__device__ __forceinline__ void st_rel(int* p, int v) {
    asm volatile("st.release.gpu.global.b32 [%0], %1;" :: "l"(p), "r"(v) : "memory");
}

// wait until tile kt's two producer blocks (2kt, 2kt+1) have published >= tgt steps.
// cf = per-(layer,warp) counter base; block nb's cell is cf + nb*8. Broadcast loads.
__device__ __forceinline__ void wait_tile(const int* cf, int kt, int tgt) {
    while (ld_acq(cf + (2 * kt) * 8) < tgt) { }
    while (ld_acq(cf + (2 * kt + 1) * 8) < tgt) { }
}

// one 16-kt half of the K sweep (2-pass fp16), 4-deep prefetch, per-tile gating:
// tile kt's prefetch waits only on its 2 producer blocks, overlapped by 4 tiles of MMA.
__device__ __forceinline__ void do_half(const uint4* __restrict__ Hq,
                                        const uint2* __restrict__ Wq,
                                        float acc[4][4],
                                        const int* cf, int tgt) {
    uint4 pa[4], pb[4];
#pragma unroll
    for (int i = 0; i < 4; i++) {
        wait_tile(cf, i, tgt);
        pa[i] = __ldcg(Hq + i * 4);
        pb[i] = __ldcg(Hq + i * 4 + 8 * 64);
    }
#pragma unroll
    for (int kt = 0; kt < 16; ++kt) {
        uint4 u1 = pa[kt & 3];
        uint4 u2 = pb[kt & 3];
        if (kt + 4 < 16) {
            wait_tile(cf, kt + 4, tgt);
            pa[kt & 3] = __ldcg(Hq + (kt + 4) * 4);
            pb[kt & 3] = __ldcg(Hq + (kt + 4) * 4 + 8 * 64);
        }
        unsigned a[4]  = {u1.x, u2.x, u1.z, u2.z};
        unsigned al[4] = {u1.y, u2.y, u1.w, u2.w};
        uint2 w0 = Wq[kt * 128 + 0];
        uint2 w1 = Wq[kt * 128 + 32];
        uint2 w2 = Wq[kt * 128 + 64];
        uint2 w3 = Wq[kt * 128 + 96];
        // pass 1: Ahi * W
        mma16816(acc[0], a,  w0.x, w0.y);
        mma16816(acc[1], a,  w1.x, w1.y);
        mma16816(acc[2], a,  w2.x, w2.y);
        mma16816(acc[3], a,  w3.x, w3.y);
        // pass 2: Alo * W
        mma16816(acc[0], al, w0.x, w0.y);
        mma16816(acc[1], al, w1.x, w1.y);
        mma16816(acc[2], al, w2.x, w2.y);
        mma16816(acc[3], al, w3.x, w3.y);
    }
}

// ---------------- prep 1: pack weights + biases + layer0 Wih ----------------
__global__ void k_prep(const float* __restrict__ Wih0, const float* __restrict__ Wihr,
                       const float* __restrict__ Whh,  const float* __restrict__ bih,
                       const float* __restrict__ bhh) {
    int idx = blockIdx.x * 256 + threadIdx.x;
    if (idx < 4 * 32 * 32 * 4 * 32) {
        int lane = idx & 31;
        int nt   = (idx >> 5) & 3;
        int kt   = (idx >> 7) & 31;
        int nb   = (idx >> 12) & 31;
        int l    = idx >> 17;
        if (l == 0 && kt >= 16) return;
        int ncol = lane >> 2;
        int r    = nt * 256 + nb * 8 + ncol;
        int k0   = kt * 16 + (lane & 3) * 2;
        __half w4[4];
#pragma unroll
        for (int q = 0; q < 4; q++) {
            int k = k0 + (q >> 1) * 8 + (q & 1);   // k0,k0+1,k0+8,k0+9
            float w;
            if (l == 0)       w = Whh[(size_t)r * H + k];
            else if (k < H)   w = Wihr[(size_t)((l - 1) * G4 + r) * H + k];
            else              w = Whh[(size_t)(l * G4 + r) * H + (k - H)];
            w4[q] = __float2half(w);
        }
        g_Wp[idx] = make_uint2(pk(w4[0], w4[1]), pk(w4[2], w4[3]));
    } else {
        int j = idx - 4 * 32 * 32 * 4 * 32;
        if (j < 4096) {
            int l = j >> 10, nb = (j >> 5) & 31, nl = j & 31;
            int r = (nl >> 3) * 256 + nb * 8 + (nl & 7);
            g_bias[j] = bih[l * G4 + r] + bhh[l * G4 + r];
        } else if (j < 4096 + 10240) {
            int jj = j - 4096;
            int nb = jj / 320, rem = jj % 320, nl = rem / 10, e = rem % 10;
            int r = (nl >> 3) * 256 + nb * 8 + (nl & 7);
            g_w0p[jj] = Wih0[r * E + e];
        }
    }
}

// ---------------- prep 2: s = relu((e01[x]+p01) @ f01_w.T + f01_b) ----------------
__global__ void k_embed(const int* __restrict__ x, const float* __restrict__ e01,
                        const float* __restrict__ p01, const float* __restrict__ f01w,
                        const float* __restrict__ f01b) {
    int idx = blockIdx.x * 256 + threadIdx.x;
    if (idx >= S * B) return;
    int t = idx / B;
    int tok = x[idx];
    float v[E];
#pragma unroll
    for (int e = 0; e < E; e++) v[e] = e01[tok * E + e] + p01[t * E + e];
    float* so = g_S + (size_t)idx * E;
#pragma unroll
    for (int i = 0; i < E; i++) {
        float a = f01b[i];
#pragma unroll
        for (int e = 0; e < E; e++) a += v[e] * f01w[i * E + e];
        so[i] = fmaxf(a, 0.0f);
    }
}

// ---------------- prep 3: ssum + h0/c0 + counter reset (fused) ----------------
__global__ void k_ssum_init(const float* __restrict__ f02w, const float* __restrict__ f02b,
                            const float* __restrict__ f03w, const float* __restrict__ f03b) {
    __shared__ float red[256 * E];
    __shared__ float ss[E];
    int b = blockIdx.x, tid = threadIdx.x;
    float acc[E];
#pragma unroll
    for (int e = 0; e < E; e++) acc[e] = 0.0f;
    for (int t = tid; t < S; t += 256) {
        const float* sp = g_S + ((size_t)t * B + b) * E;
#pragma unroll
        for (int e = 0; e < E; e++) acc[e] += sp[e];
    }
#pragma unroll
    for (int e = 0; e < E; e++) red[tid * E + e] = acc[e];
    __syncthreads();
    for (int s = 128; s > 0; s >>= 1) {
        if (tid < s) {
#pragma unroll
            for (int e = 0; e < E; e++) red[tid * E + e] += red[(tid + s) * E + e];
        }
        __syncthreads();
    }
    if (tid < E) ss[tid] = red[tid];
    if (b == 0) for (int i = tid; i < L * 32 * 8; i += 256) g_fine[i] = 0;
    __syncthreads();
    __half* Hb = (__half*)g_Hq;
#pragma unroll
    for (int i = 0; i < 4; i++) {
        int r = tid + i * 256;           // gate row 0..1023
        float ah = f02b[r], ac = f03b[r];
#pragma unroll
        for (int e = 0; e < E; e++) {
            ah += ss[e] * f02w[r * E + e];
            ac += ss[e] * f03w[r * E + e];
        }
        ah = fmaxf(ah, 0.0f);
        ac = fmaxf(ac, 0.0f);
        int l = r >> 8, j = r & 255;
        int u = unitj(j & ~1);
        // initial h = "step -1" output -> slot 3 ((-1) & 3)
        size_t base = (((size_t)(l * 4 + 3) * B) + b) * 512 + u * 4 + (j & 1);
        __half hh = __float2half(ah);
        Hb[base]     = hh;
        Hb[base + 2] = __float2half(ah - __half2float(hh));
        g_C0[((size_t)l * B + b) * H + j] = ac;
    }
}

// ---------------- persistent recurrent kernel: per-warp, per-tile-gated pipeline ----------------
__global__ void __launch_bounds__(256, 1) lstm_rec(float* __restrict__ out) {
    const int bid = blockIdx.x;
    const int l   = bid >> 5;
    const int nb  = bid & 31;
    const int tid = threadIdx.x;
    const int warp = tid >> 5;
    const int lane = tid & 31;

    extern __shared__ unsigned char smem[];
    uint2* Wsm  = (uint2*)smem;                 // [32][4][32] uint2 = 32KB
    float* bsm  = (float*)(Wsm + 4096);         // 32
    float* w0sm = bsm + 32;                     // 320 (layer 0 only)

    const int Kkt = (l == 0) ? 16 : 32;
    {
        const uint2* src = g_Wp + (size_t)(l * 32 + nb) * 4096;
        for (int i = tid; i < Kkt * 128; i += 256) Wsm[i] = src[i];
        if (tid < 32) bsm[tid] = g_bias[(l * 32 + nb) * 32 + tid];
        if (l == 0) for (int i = tid; i < 320; i += 256) w0sm[i] = g_w0p[nb * 320 + i];
    }

    const int qd  = lane & 3;
    const int r0  = lane >> 2;
    const int c2  = qd * 2;
    const int b0  = warp * 16 + r0;
    const int jj0 = nb * 8 + c2;
    const int ust = unitj(jj0);                 // store unit within row

    float cst[4];
    cst[0] = g_C0[((size_t)l * B + b0) * H + jj0];
    cst[1] = g_C0[((size_t)l * B + b0) * H + jj0 + 1];
    cst[2] = g_C0[((size_t)l * B + b0 + 8) * H + jj0];
    cst[3] = g_C0[((size_t)l * B + b0 + 8) * H + jj0 + 1];
    __syncthreads();

    // per-lane smem weight pointers
    const uint2* WqIn  = Wsm + lane;                       // input half (l>0): kt 0..15
    const uint2* WqOwn = Wsm + (l ? 16 * 128 : 0) + lane;  // Whh half

    // fine counter bases: cell for block nb' is base + nb'*8
    const int* cfOwn = g_fine + l * 256 + warp;
    const int* cfIn  = (l > 0) ? g_fine + (l - 1) * 256 + warp : nullptr;
    const int* cfDn  = (l < 3) ? g_fine + (l + 1) * 256 + warp : nullptr;
    int* myCnt = g_fine + l * 256 + nb * 8 + warp;

    const size_t laneOfs = (size_t)b0 * 64 + qd;

    float bias_r[4][2];
#pragma unroll
    for (int nt = 0; nt < 4; nt++) {
        bias_r[nt][0] = bsm[nt * 8 + c2];
        bias_r[nt][1] = bsm[nt * 8 + c2 + 1];
    }

    for (int t = 0; t < S; ++t) {
        const int scur  = t & 3;            // slot written this step
        const int sprev = (t + 3) & 3;      // own h from step t-1

        float acc[4][4];
#pragma unroll
        for (int nt = 0; nt < 4; nt++) {
#pragma unroll
            for (int rg = 0; rg < 4; rg++)
                acc[nt][rg] = bias_r[nt][rg & 1];
        }

        if (l > 0) {
            // INPUT HALF FIRST (layer below runs ahead -> tile gates pre-satisfied);
            // hides the own-layer publish->detect->load round trip.
            do_half(g_Hq + (size_t)((l - 1) * 4 + scur) * B * 64 + laneOfs,
                    WqIn, acc, cfIn, t + 1);
            // OWN Whh HALF: per-tile gates replace the max-of-32 wait; each tile
            // waits only on its 2 producer blocks, overlapped by 4 tiles of MMA.
            do_half(g_Hq + (size_t)(l * 4 + sprev) * B * 64 + laneOfs,
                    WqOwn, acc, cfOwn, t);
        } else {
            // E=10 input contribution (independent of all counters)
            float sv0[E], sv1[E];
            const float* sp = g_S + ((size_t)t * B + b0) * E;
#pragma unroll
            for (int e = 0; e < E; e++) { sv0[e] = sp[e]; sv1[e] = sp[8 * E + e]; }
#pragma unroll
            for (int nt = 0; nt < 4; nt++) {
                const float* wA = w0sm + (nt * 8 + c2) * E;
                const float* wB = wA + E;
#pragma unroll
                for (int e = 0; e < E; e++) {
                    acc[nt][0] += sv0[e] * wA[e];
                    acc[nt][1] += sv0[e] * wB[e];
                    acc[nt][2] += sv1[e] * wA[e];
                    acc[nt][3] += sv1[e] * wB[e];
                }
            }
            do_half(g_Hq + (size_t)(l * 4 + sprev) * B * 64 + laneOfs,
                    WqOwn, acc, cfOwn, t);
        }

        // epilogue
        float hv[4];
#pragma unroll
        for (int rg = 0; rg < 4; rg++) {
            float iv = fsig(acc[0][rg]);
            float fv = fsig(acc[1][rg]);
            float gv = ftanh(acc[2][rg]);
            float ov = fsig(acc[3][rg]);
            float cv = fv * cst[rg] + iv * gv;
            cst[rg] = cv;
            hv[rg] = ov * ftanh(cv);
        }

        // anti-overwrite: layer above must have completed step t-4 (lane-parallel check)
        if (l < 3 && t >= 4) {
            int c = ld_acq(cfDn + lane * 8);
            while (__ballot_sync(0xffffffffu, c < t - 3))
                c = ld_acq(cfDn + lane * 8);
        }

        unsigned long long* Ow =
            (unsigned long long*)(g_Hq + (size_t)(l * 4 + scur) * B * 64);
#pragma unroll
        for (int half = 0; half < 2; half++) {
            float h0v = hv[half * 2], h1v = hv[half * 2 + 1];
            int row = b0 + half * 8;
            __half hh0 = __float2half(h0v);
            __half hh1 = __float2half(h1v);
            unsigned lo32 = pk(hh0, hh1);
            unsigned hi32 = pk(__float2half(h0v - __half2float(hh0)),
                               __float2half(h1v - __half2float(hh1)));
            unsigned long long val = (unsigned long long)lo32 |
                                     ((unsigned long long)hi32 << 32);
            Ow[(size_t)row * 128 + ust] = val;
            if (t == S - 1) {
                float2 o2 = make_float2(h0v, h1v);
                *(float2*)(out + (size_t)row * G4 + l * H + jj0) = o2;
            }
        }

        __syncwarp();
        if (lane == 0) st_rel(myCnt, t + 1);
    }
}

// ---------------- launch ----------------
extern "C" void kernel_launch(void* const* d_in, const int* in_sizes, int n_in,
                              void* d_out, int out_size) {
    const int*   x    = (const int*)d_in[0];
    const float* e01  = (const float*)d_in[1];
    const float* p01  = (const float*)d_in[2];
    const float* f01w = (const float*)d_in[3];
    const float* f01b = (const float*)d_in[4];
    const float* f02w = (const float*)d_in[5];
    const float* f02b = (const float*)d_in[6];
    const float* f03w = (const float*)d_in[7];
    const float* f03b = (const float*)d_in[8];
    const float* Wih0 = (const float*)d_in[9];
    const float* Wihr = (const float*)d_in[10];
    const float* Whh  = (const float*)d_in[11];
    const float* bih  = (const float*)d_in[12];
    const float* bhh  = (const float*)d_in[13];
    float* out = (float*)d_out;

    k_prep<<<(4 * 32 * 32 * 4 * 32 + 4096 + 10240 + 255) / 256, 256>>>(Wih0, Wihr, Whh, bih, bhh);
    k_embed<<<(S * B + 255) / 256, 256>>>(x, e01, p01, f01w, f01b);
    k_ssum_init<<<B, 256>>>(f02w, f02b, f03w, f03b);

    const int smem_bytes = 4096 * 8 + (32 + 320) * 4;  // ~34KB
    cudaFuncSetAttribute(lstm_rec, cudaFuncAttributeMaxDynamicSharedMemorySize,
                         smem_bytes);
    lstm_rec<<<NBLK, 256, smem_bytes>>>(out);
}

// round 17
// speedup vs baseline: 3.4343x; 3.4343x over previous
#include <cuda_runtime.h>
#include <cuda_fp16.h>
#include <math.h>

#define S 1024
#define B 128
#define E 10
#define H 256
#define L 4
#define G4 1024           // 4*H
#define NBPL 32           // blocks per layer
#define NBLK (NBPL * L)   // 128 persistent blocks

// ---------------- device scratch (static; no allocations) ----------------
// fp16 weight fragments: [l][nb][kt][nt][lane] = uint2(w.k01, w.k89)
__device__ __align__(8) uint2  g_Wp[4 * 32 * 32 * 4 * 32];
__device__ float  g_bias[4 * 32 * 32];
__device__ float  g_w0p[32 * 32 * 10];
__device__ float  g_S[S * B * E];
__device__ float  g_C0[L * B * H];
// h state: [l][slot(4)][b][64 uint4]; u64 unit = (hi(j),hi(j+1),lo(j),lo(j+1)) fp16
__device__ __align__(16) uint4 g_Hq[L * 4 * B * 64];
// single-writer step cells: [l][warp][nb] = steps published by block nb's warp (t+1)
__device__ __align__(128) int g_cnt[L * 8 * 32];

// ---------------- helpers ----------------
// perm-unit index for even col j: u64-unit within row
__device__ __host__ __forceinline__ int unitj(int j) {
    return (j >> 4) * 8 + (j & 6) + ((j >> 3) & 1);
}

__device__ __forceinline__ unsigned pk(__half a, __half b) {
    __half2 t; t.x = a; t.y = b;
    return *reinterpret_cast<unsigned*>(&t);
}

__device__ __forceinline__ void mma16816(float c[4], const unsigned a[4],
                                         unsigned b0, unsigned b1) {
    asm("mma.sync.aligned.m16n8k16.row.col.f32.f16.f16.f32 "
        "{%0,%1,%2,%3},{%4,%5,%6,%7},{%8,%9},{%0,%1,%2,%3};"
        : "+f"(c[0]), "+f"(c[1]), "+f"(c[2]), "+f"(c[3])
        : "r"(a[0]), "r"(a[1]), "r"(a[2]), "r"(a[3]), "r"(b0), "r"(b1));
}

__device__ __forceinline__ float fsig(float x) {
    return __fdividef(1.0f, 1.0f + __expf(-x));
}
__device__ __forceinline__ float ftanh(float x) {
    return 1.0f - __fdividef(2.0f, __expf(2.0f * x) + 1.0f);
}

__device__ __forceinline__ int ld_acq(const int* p) {
    int v;
    asm volatile("ld.acquire.gpu.global.b32 %0, [%1];" : "=r"(v) : "l"(p) : "memory");
    return v;
}
__device__ __forceinline__ void st_rel(int* p, int v) {
    asm volatile("st.release.gpu.global.b32 [%0], %1;" :: "l"(p), "r"(v) : "memory");
}

// wait until ALL 32 blocks' cells in one 128B row reach tgt: one coalesced
// lane-parallel load + ballot per iteration (no atomic drain on the producer side).
__device__ __forceinline__ void wait_all(const int* row, int lane, int tgt) {
    int c = ld_acq(row + lane);
    while (!__all_sync(0xffffffffu, c >= tgt))
        c = ld_acq(row + lane);
}

// one 16-kt half of the K sweep (2-pass fp16), 4-deep activation prefetch.
// Hq = per-lane activation ptr (kt=0), Wq = per-lane smem ptr (kt=0)
__device__ __forceinline__ void do_half(const uint4* __restrict__ Hq,
                                        const uint2* __restrict__ Wq,
                                        float acc[4][4]) {
    uint4 pa[4], pb[4];
#pragma unroll
    for (int i = 0; i < 4; i++) {
        pa[i] = __ldcg(Hq + i * 4);
        pb[i] = __ldcg(Hq + i * 4 + 8 * 64);
    }
#pragma unroll
    for (int kt = 0; kt < 16; ++kt) {
        uint4 u1 = pa[kt & 3];
        uint4 u2 = pb[kt & 3];
        if (kt + 4 < 16) {
            pa[kt & 3] = __ldcg(Hq + (kt + 4) * 4);
            pb[kt & 3] = __ldcg(Hq + (kt + 4) * 4 + 8 * 64);
        }
        unsigned a[4]  = {u1.x, u2.x, u1.z, u2.z};
        unsigned al[4] = {u1.y, u2.y, u1.w, u2.w};
        uint2 w0 = Wq[kt * 128 + 0];
        uint2 w1 = Wq[kt * 128 + 32];
        uint2 w2 = Wq[kt * 128 + 64];
        uint2 w3 = Wq[kt * 128 + 96];
        // pass 1: Ahi * W
        mma16816(acc[0], a,  w0.x, w0.y);
        mma16816(acc[1], a,  w1.x, w1.y);
        mma16816(acc[2], a,  w2.x, w2.y);
        mma16816(acc[3], a,  w3.x, w3.y);
        // pass 2: Alo * W
        mma16816(acc[0], al, w0.x, w0.y);
        mma16816(acc[1], al, w1.x, w1.y);
        mma16816(acc[2], al, w2.x, w2.y);
        mma16816(acc[3], al, w3.x, w3.y);
    }
}

// ---------------- prep 1: pack weights + biases + layer0 Wih ----------------
__global__ void k_prep(const float* __restrict__ Wih0, const float* __restrict__ Wihr,
                       const float* __restrict__ Whh,  const float* __restrict__ bih,
                       const float* __restrict__ bhh) {
    int idx = blockIdx.x * 256 + threadIdx.x;
    if (idx < 4 * 32 * 32 * 4 * 32) {
        int lane = idx & 31;
        int nt   = (idx >> 5) & 3;
        int kt   = (idx >> 7) & 31;
        int nb   = (idx >> 12) & 31;
        int l    = idx >> 17;
        if (l == 0 && kt >= 16) return;
        int ncol = lane >> 2;
        int r    = nt * 256 + nb * 8 + ncol;
        int k0   = kt * 16 + (lane & 3) * 2;
        __half w4[4];
#pragma unroll
        for (int q = 0; q < 4; q++) {
            int k = k0 + (q >> 1) * 8 + (q & 1);   // k0,k0+1,k0+8,k0+9
            float w;
            if (l == 0)       w = Whh[(size_t)r * H + k];
            else if (k < H)   w = Wihr[(size_t)((l - 1) * G4 + r) * H + k];
            else              w = Whh[(size_t)(l * G4 + r) * H + (k - H)];
            w4[q] = __float2half(w);
        }
        g_Wp[idx] = make_uint2(pk(w4[0], w4[1]), pk(w4[2], w4[3]));
    } else {
        int j = idx - 4 * 32 * 32 * 4 * 32;
        if (j < 4096) {
            int l = j >> 10, nb = (j >> 5) & 31, nl = j & 31;
            int r = (nl >> 3) * 256 + nb * 8 + (nl & 7);
            g_bias[j] = bih[l * G4 + r] + bhh[l * G4 + r];
        } else if (j < 4096 + 10240) {
            int jj = j - 4096;
            int nb = jj / 320, rem = jj % 320, nl = rem / 10, e = rem % 10;
            int r = (nl >> 3) * 256 + nb * 8 + (nl & 7);
            g_w0p[jj] = Wih0[r * E + e];
        }
    }
}

// ---------------- prep 2: s = relu((e01[x]+p01) @ f01_w.T + f01_b) ----------------
__global__ void k_embed(const int* __restrict__ x, const float* __restrict__ e01,
                        const float* __restrict__ p01, const float* __restrict__ f01w,
                        const float* __restrict__ f01b) {
    int idx = blockIdx.x * 256 + threadIdx.x;
    if (idx >= S * B) return;
    int t = idx / B;
    int tok = x[idx];
    float v[E];
#pragma unroll
    for (int e = 0; e < E; e++) v[e] = e01[tok * E + e] + p01[t * E + e];
    float* so = g_S + (size_t)idx * E;
#pragma unroll
    for (int i = 0; i < E; i++) {
        float a = f01b[i];
#pragma unroll
        for (int e = 0; e < E; e++) a += v[e] * f01w[i * E + e];
        so[i] = fmaxf(a, 0.0f);
    }
}

// ---------------- prep 3: ssum + h0/c0 + counter reset (fused) ----------------
__global__ void k_ssum_init(const float* __restrict__ f02w, const float* __restrict__ f02b,
                            const float* __restrict__ f03w, const float* __restrict__ f03b) {
    __shared__ float red[256 * E];
    __shared__ float ss[E];
    int b = blockIdx.x, tid = threadIdx.x;
    float acc[E];
#pragma unroll
    for (int e = 0; e < E; e++) acc[e] = 0.0f;
    for (int t = tid; t < S; t += 256) {
        const float* sp = g_S + ((size_t)t * B + b) * E;
#pragma unroll
        for (int e = 0; e < E; e++) acc[e] += sp[e];
    }
#pragma unroll
    for (int e = 0; e < E; e++) red[tid * E + e] = acc[e];
    __syncthreads();
    for (int s = 128; s > 0; s >>= 1) {
        if (tid < s) {
#pragma unroll
            for (int e = 0; e < E; e++) red[tid * E + e] += red[(tid + s) * E + e];
        }
        __syncthreads();
    }
    if (tid < E) ss[tid] = red[tid];
    if (b == 0) for (int i = tid; i < L * 8 * 32; i += 256) g_cnt[i] = 0;
    __syncthreads();
    __half* Hb = (__half*)g_Hq;
#pragma unroll
    for (int i = 0; i < 4; i++) {
        int r = tid + i * 256;           // gate row 0..1023
        float ah = f02b[r], ac = f03b[r];
#pragma unroll
        for (int e = 0; e < E; e++) {
            ah += ss[e] * f02w[r * E + e];
            ac += ss[e] * f03w[r * E + e];
        }
        ah = fmaxf(ah, 0.0f);
        ac = fmaxf(ac, 0.0f);
        int l = r >> 8, j = r & 255;
        int u = unitj(j & ~1);
        // initial h = "step -1" output -> slot 3 ((-1) & 3)
        size_t base = (((size_t)(l * 4 + 3) * B) + b) * 512 + u * 4 + (j & 1);
        __half hh = __float2half(ah);
        Hb[base]     = hh;
        Hb[base + 2] = __float2half(ah - __half2float(hh));
        g_C0[((size_t)l * B + b) * H + j] = ac;
    }
}

// ---------------- persistent recurrent kernel: per-warp decoupled pipeline ----------------
// Input-half-first ordering hides the own-layer publish->detect->load round trip.
// Single-writer step cells + one-line ballot detect remove the 32-way same-address
// atomic drain from the publish path.
__global__ void __launch_bounds__(256, 1) lstm_rec(float* __restrict__ out) {
    const int bid = blockIdx.x;
    const int l   = bid >> 5;
    const int nb  = bid & 31;
    const int tid = threadIdx.x;
    const int warp = tid >> 5;
    const int lane = tid & 31;

    extern __shared__ unsigned char smem[];
    uint2* Wsm  = (uint2*)smem;                 // [32][4][32] uint2 = 32KB
    float* bsm  = (float*)(Wsm + 4096);         // 32
    float* w0sm = bsm + 32;                     // 320 (layer 0 only)

    const int Kkt = (l == 0) ? 16 : 32;
    {
        const uint2* src = g_Wp + (size_t)(l * 32 + nb) * 4096;
        for (int i = tid; i < Kkt * 128; i += 256) Wsm[i] = src[i];
        if (tid < 32) bsm[tid] = g_bias[(l * 32 + nb) * 32 + tid];
        if (l == 0) for (int i = tid; i < 320; i += 256) w0sm[i] = g_w0p[nb * 320 + i];
    }

    const int qd  = lane & 3;
    const int r0  = lane >> 2;
    const int c2  = qd * 2;
    const int b0  = warp * 16 + r0;
    const int jj0 = nb * 8 + c2;
    const int ust = unitj(jj0);                 // store unit within row

    float cst[4];
    cst[0] = g_C0[((size_t)l * B + b0) * H + jj0];
    cst[1] = g_C0[((size_t)l * B + b0) * H + jj0 + 1];
    cst[2] = g_C0[((size_t)l * B + b0 + 8) * H + jj0];
    cst[3] = g_C0[((size_t)l * B + b0 + 8) * H + jj0 + 1];
    __syncthreads();

    // per-lane smem weight pointers
    const uint2* WqIn  = Wsm + lane;                       // input half (l>0): kt 0..15
    const uint2* WqOwn = Wsm + (l ? 16 * 128 : 0) + lane;  // Whh half

    // counter rows: [l][warp][nb] -- 32 consecutive ints per (l,warp) = one 128B line
    const int* rowOwn = g_cnt + (l * 8 + warp) * 32;
    const int* rowIn  = (l > 0) ? g_cnt + ((l - 1) * 8 + warp) * 32 : nullptr;
    const int* rowDn  = (l < 3) ? g_cnt + ((l + 1) * 8 + warp) * 32 : nullptr;
    int* myCell = g_cnt + (l * 8 + warp) * 32 + nb;

    // slot bases (uint4 index): slot s of layer l at (l*4+s)*B*64
    const size_t laneOfs = (size_t)b0 * 64 + qd;

    float bias_r[4][2];
#pragma unroll
    for (int nt = 0; nt < 4; nt++) {
        bias_r[nt][0] = bsm[nt * 8 + c2];
        bias_r[nt][1] = bsm[nt * 8 + c2 + 1];
    }

    for (int t = 0; t < S; ++t) {
        const int scur  = t & 3;            // slot written this step
        const int sprev = (t + 3) & 3;      // own h from step t-1

        float acc[4][4];
#pragma unroll
        for (int nt = 0; nt < 4; nt++) {
#pragma unroll
            for (int rg = 0; rg < 4; rg++)
                acc[nt][rg] = bias_r[nt][rg & 1];
        }

        if (l > 0) {
            // INPUT HALF FIRST: depends only on layer l-1 (runs ahead -> poll cheap).
            wait_all(rowIn, lane, t + 1);
            do_half(g_Hq + (size_t)((l - 1) * 4 + scur) * B * 64 + laneOfs, WqIn, acc);

            if (t > 0) wait_all(rowOwn, lane, t);
            do_half(g_Hq + (size_t)(l * 4 + sprev) * B * 64 + laneOfs, WqOwn, acc);
        } else {
            // E=10 input contribution (independent of all counters)
            float sv0[E], sv1[E];
            const float* sp = g_S + ((size_t)t * B + b0) * E;
#pragma unroll
            for (int e = 0; e < E; e++) { sv0[e] = sp[e]; sv1[e] = sp[8 * E + e]; }
#pragma unroll
            for (int nt = 0; nt < 4; nt++) {
                const float* wA = w0sm + (nt * 8 + c2) * E;
                const float* wB = wA + E;
#pragma unroll
                for (int e = 0; e < E; e++) {
                    acc[nt][0] += sv0[e] * wA[e];
                    acc[nt][1] += sv0[e] * wB[e];
                    acc[nt][2] += sv1[e] * wA[e];
                    acc[nt][3] += sv1[e] * wB[e];
                }
            }
            if (t > 0) wait_all(rowOwn, lane, t);
            do_half(g_Hq + (size_t)(l * 4 + sprev) * B * 64 + laneOfs, WqOwn, acc);
        }

        // epilogue
        float hv[4];
#pragma unroll
        for (int rg = 0; rg < 4; rg++) {
            float iv = fsig(acc[0][rg]);
            float fv = fsig(acc[1][rg]);
            float gv = ftanh(acc[2][rg]);
            float ov = fsig(acc[3][rg]);
            float cv = fv * cst[rg] + iv * gv;
            cst[rg] = cv;
            hv[rg] = ov * ftanh(cv);
        }

        // anti-overwrite: layer above consumed h[t-4] (gates only the store)
        if (l < 3 && t >= 4) wait_all(rowDn, lane, t - 3);

        unsigned long long* Ow =
            (unsigned long long*)(g_Hq + (size_t)(l * 4 + scur) * B * 64);
#pragma unroll
        for (int half = 0; half < 2; half++) {
            float h0v = hv[half * 2], h1v = hv[half * 2 + 1];
            int row = b0 + half * 8;
            __half hh0 = __float2half(h0v);
            __half hh1 = __float2half(h1v);
            unsigned lo32 = pk(hh0, hh1);
            unsigned hi32 = pk(__float2half(h0v - __half2float(hh0)),
                               __float2half(h1v - __half2float(hh1)));
            unsigned long long val = (unsigned long long)lo32 |
                                     ((unsigned long long)hi32 << 32);
            Ow[(size_t)row * 128 + ust] = val;
            if (t == S - 1) {
                float2 o2 = make_float2(h0v, h1v);
                *(float2*)(out + (size_t)row * G4 + l * H + jj0) = o2;
            }
        }

        __syncwarp();
        if (lane == 0) st_rel(myCell, t + 1);   // single-writer publish: no atomic drain
    }
}

// ---------------- launch ----------------
extern "C" void kernel_launch(void* const* d_in, const int* in_sizes, int n_in,
                              void* d_out, int out_size) {
    const int*   x    = (const int*)d_in[0];
    const float* e01  = (const float*)d_in[1];
    const float* p01  = (const float*)d_in[2];
    const float* f01w = (const float*)d_in[3];
    const float* f01b = (const float*)d_in[4];
    const float* f02w = (const float*)d_in[5];
    const float* f02b = (const float*)d_in[6];
    const float* f03w = (const float*)d_in[7];
    const float* f03b = (const float*)d_in[8];
    const float* Wih0 = (const float*)d_in[9];
    const float* Wihr = (const float*)d_in[10];
    const float* Whh  = (const float*)d_in[11];
    const float* bih  = (const float*)d_in[12];
    const float* bhh  = (const float*)d_in[13];
    float* out = (float*)d_out;

    k_prep<<<(4 * 32 * 32 * 4 * 32 + 4096 + 10240 + 255) / 256, 256>>>(Wih0, Wihr, Whh, bih, bhh);
    k_embed<<<(S * B + 255) / 256, 256>>>(x, e01, p01, f01w, f01b);
    k_ssum_init<<<B, 256>>>(f02w, f02b, f03w, f03b);

    const int smem_bytes = 4096 * 8 + (32 + 320) * 4;  // ~34KB
    cudaFuncSetAttribute(lstm_rec, cudaFuncAttributeMaxDynamicSharedMemorySize,
                         smem_bytes);
    lstm_rec<<<NBLK, 256, smem_bytes>>>(out);
}